// round 1
// baseline (speedup 1.0000x reference)
#include <cuda_runtime.h>

// Batched per-object MLP:
//   y1 = W1 @ x + b1                  [256]   (no activation)
//   y2 = sigmoid(W2 @ y1 + b2)        [256]
//   out = sigmoid(W3 @ y2 + b3)       scalar
// One CTA per object. Pure HBM-streaming kernel: every weight byte read
// exactly once via coalesced float4 LDG.

#define N_OBJ_  2048
#define IN_DIM_ 128
#define MID_    256

__device__ __forceinline__ float warp_sum(float v) {
#pragma unroll
    for (int off = 16; off > 0; off >>= 1)
        v += __shfl_xor_sync(0xffffffffu, v, off);
    return v;
}

__device__ __forceinline__ float sigmoidf_(float t) {
    return 1.0f / (1.0f + __expf(-t));
}

__global__ __launch_bounds__(256, 8)
void mlp_obj_kernel(const float* __restrict__ x,
                    const float* __restrict__ W1,
                    const float* __restrict__ b1,
                    const float* __restrict__ W2,
                    const float* __restrict__ b2,
                    const float* __restrict__ W3,
                    const float* __restrict__ b3,
                    float* __restrict__ out)
{
    const int o    = blockIdx.x;
    const int tid  = threadIdx.x;
    const int warp = tid >> 5;
    const int lane = tid & 31;

    __shared__ float y1[MID_];
    __shared__ float y2[MID_];

    // ---- Phase 1: y1 = W1 @ x + b1 ----------------------------------
    // lane's 4-element fragment of x (reused across all 32 rows this warp does)
    const float4 xv =
        reinterpret_cast<const float4*>(x + (size_t)o * IN_DIM_)[lane];

    const float* W1o = W1 + (size_t)o * MID_ * IN_DIM_;
    const float* b1o = b1 + (size_t)o * MID_;

#pragma unroll 4
    for (int j = 0; j < 32; ++j) {
        const int row = warp * 32 + j;
        const float4 w =
            reinterpret_cast<const float4*>(W1o + (size_t)row * IN_DIM_)[lane];
        float s = w.x * xv.x + w.y * xv.y + w.z * xv.z + w.w * xv.w;
        s = warp_sum(s);
        if (lane == 0) y1[row] = s + b1o[row];
    }
    __syncthreads();

    // ---- Phase 2: y2 = sigmoid(W2 @ y1 + b2) -------------------------
    // lane's two 4-element fragments of y1 (cols lane*4.. and 128+lane*4..)
    const float4 y1a = reinterpret_cast<const float4*>(y1)[lane];
    const float4 y1b = reinterpret_cast<const float4*>(y1)[32 + lane];

    const float* W2o = W2 + (size_t)o * MID_ * MID_;
    const float* b2o = b2 + (size_t)o * MID_;

#pragma unroll 4
    for (int j = 0; j < 32; ++j) {
        const int row = warp * 32 + j;
        const float4* wr =
            reinterpret_cast<const float4*>(W2o + (size_t)row * MID_);
        const float4 wa = wr[lane];
        const float4 wb = wr[32 + lane];
        float s = wa.x * y1a.x + wa.y * y1a.y + wa.z * y1a.z + wa.w * y1a.w
                + wb.x * y1b.x + wb.y * y1b.y + wb.z * y1b.z + wb.w * y1b.w;
        s = warp_sum(s);
        if (lane == 0) y2[row] = sigmoidf_(s + b2o[row]);
    }
    __syncthreads();

    // ---- Phase 3: out = sigmoid(W3 @ y2 + b3) ------------------------
    if (warp == 0) {
        const float4* w3v =
            reinterpret_cast<const float4*>(W3 + (size_t)o * MID_);
        const float4* y2v = reinterpret_cast<const float4*>(y2);
        const float4 wa = w3v[lane],      wb = w3v[32 + lane];
        const float4 ya = y2v[lane],      yb = y2v[32 + lane];
        float s = wa.x * ya.x + wa.y * ya.y + wa.z * ya.z + wa.w * ya.w
                + wb.x * yb.x + wb.y * yb.y + wb.z * yb.z + wb.w * yb.w;
        s = warp_sum(s);
        if (lane == 0) out[o] = sigmoidf_(s + b3[o]);
    }
}

extern "C" void kernel_launch(void* const* d_in, const int* in_sizes, int n_in,
                              void* d_out, int out_size)
{
    const float* x  = (const float*)d_in[0];
    const float* W1 = (const float*)d_in[1];
    const float* b1 = (const float*)d_in[2];
    const float* W2 = (const float*)d_in[3];
    const float* b2 = (const float*)d_in[4];
    const float* W3 = (const float*)d_in[5];
    const float* b3 = (const float*)d_in[6];
    float* out = (float*)d_out;

    mlp_obj_kernel<<<N_OBJ_, 256>>>(x, W1, b1, W2, b2, W3, b3, out);
}

// round 2
// speedup vs baseline: 1.0308x; 1.0308x over previous
#include <cuda_runtime.h>

// Batched per-object 3-layer MLP, split into 3 fine-grained kernels to kill
// the drain tail. Intermediates staged via __device__ globals (L2-resident).
//
//   K1: y1 = W1 @ x + b1          (reads 256 MB of W1)
//   K2: y2 = sigmoid(W2 @ y1 + b2)(reads 512 MB of W2)
//   K3: out = sigmoid(W3 . y2 + b3)
//
// Each K1/K2 CTA handles 32 rows of one object (~16-32 KB of weights,
// ~0.7 us) so the grid load-balances to within one tiny CTA.

#define N_OBJ_  2048
#define IN_DIM_ 128
#define MID_    256
#define CHUNKS_ 8          // 256 rows / 32 rows per CTA

__device__ float g_y1[N_OBJ_ * MID_];
__device__ float g_y2[N_OBJ_ * MID_];

__device__ __forceinline__ float warp_sum(float v) {
#pragma unroll
    for (int off = 16; off > 0; off >>= 1)
        v += __shfl_xor_sync(0xffffffffu, v, off);
    return v;
}

__device__ __forceinline__ float sigmoidf_(float t) {
    return 1.0f / (1.0f + __expf(-t));
}

// ---- K1: y1 rows. 128 threads = 4 warps, 8 rows per warp, 32 rows/CTA ----
__global__ __launch_bounds__(128, 16)
void k1_fc1(const float* __restrict__ x,
            const float* __restrict__ W1,
            const float* __restrict__ b1)
{
    const int o     = blockIdx.x >> 3;       // object
    const int chunk = blockIdx.x & 7;        // which 32-row slab
    const int warp  = threadIdx.x >> 5;
    const int lane  = threadIdx.x & 31;

    const float4 xv =
        reinterpret_cast<const float4*>(x + (size_t)o * IN_DIM_)[lane];
    const float* W1o = W1 + (size_t)o * MID_ * IN_DIM_;
    const int row0 = chunk * 32 + warp * 8;

#pragma unroll
    for (int j = 0; j < 8; ++j) {
        const int row = row0 + j;
        const float4 w =
            reinterpret_cast<const float4*>(W1o + (size_t)row * IN_DIM_)[lane];
        float s = fmaf(w.x, xv.x, fmaf(w.y, xv.y, fmaf(w.z, xv.z, w.w * xv.w)));
        s = warp_sum(s);
        if (lane == 0)
            g_y1[o * MID_ + row] = s + b1[o * MID_ + row];
    }
}

// ---- K2: y2 rows. Same shape; rows are 256 wide (2 float4 per lane) ----
__global__ __launch_bounds__(128, 16)
void k2_fc2(const float* __restrict__ W2,
            const float* __restrict__ b2)
{
    const int o     = blockIdx.x >> 3;
    const int chunk = blockIdx.x & 7;
    const int warp  = threadIdx.x >> 5;
    const int lane  = threadIdx.x & 31;

    const float4* y1v = reinterpret_cast<const float4*>(g_y1 + o * MID_);
    const float4 ya = y1v[lane];
    const float4 yb = y1v[32 + lane];

    const float* W2o = W2 + (size_t)o * MID_ * MID_;
    const int row0 = chunk * 32 + warp * 8;

#pragma unroll
    for (int j = 0; j < 8; ++j) {
        const int row = row0 + j;
        const float4* wr =
            reinterpret_cast<const float4*>(W2o + (size_t)row * MID_);
        const float4 wa = wr[lane];
        const float4 wb = wr[32 + lane];
        float s = fmaf(wa.x, ya.x, fmaf(wa.y, ya.y,
                  fmaf(wa.z, ya.z, fmaf(wa.w, ya.w,
                  fmaf(wb.x, yb.x, fmaf(wb.y, yb.y,
                  fmaf(wb.z, yb.z, wb.w * yb.w)))))));
        s = warp_sum(s);
        if (lane == 0)
            g_y2[o * MID_ + row] = sigmoidf_(s + b2[o * MID_ + row]);
    }
}

// ---- K3: final dot + sigmoid. One warp per object. ----
__global__ __launch_bounds__(256, 8)
void k3_out(const float* __restrict__ W3,
            const float* __restrict__ b3,
            float* __restrict__ out)
{
    const int warp = threadIdx.x >> 5;
    const int lane = threadIdx.x & 31;
    const int o = blockIdx.x * 8 + warp;

    const float4* w3v = reinterpret_cast<const float4*>(W3 + (size_t)o * MID_);
    const float4* y2v = reinterpret_cast<const float4*>(g_y2 + o * MID_);
    const float4 wa = w3v[lane],      wb = w3v[32 + lane];
    const float4 ya = y2v[lane],      yb = y2v[32 + lane];
    float s = fmaf(wa.x, ya.x, fmaf(wa.y, ya.y,
              fmaf(wa.z, ya.z, fmaf(wa.w, ya.w,
              fmaf(wb.x, yb.x, fmaf(wb.y, yb.y,
              fmaf(wb.z, yb.z, wb.w * yb.w)))))));
    s = warp_sum(s);
    if (lane == 0) out[o] = sigmoidf_(s + b3[o]);
}

extern "C" void kernel_launch(void* const* d_in, const int* in_sizes, int n_in,
                              void* d_out, int out_size)
{
    const float* x  = (const float*)d_in[0];
    const float* W1 = (const float*)d_in[1];
    const float* b1 = (const float*)d_in[2];
    const float* W2 = (const float*)d_in[3];
    const float* b2 = (const float*)d_in[4];
    const float* W3 = (const float*)d_in[5];
    const float* b3 = (const float*)d_in[6];
    float* out = (float*)d_out;

    k1_fc1<<<N_OBJ_ * CHUNKS_, 128>>>(x, W1, b1);
    k2_fc2<<<N_OBJ_ * CHUNKS_, 128>>>(W2, b2);
    k3_out<<<N_OBJ_ / 8, 256>>>(W3, b3, out);
}